// round 15
// baseline (speedup 1.0000x reference)
#include <cuda_runtime.h>
#include <math.h>

#define NTOK 176

__device__ float g_KT[2048 * 64 * 176];
__device__ float g_V [2048 * 176 * 64];
__device__ float g_QT[2048 * 64 * 128];

#define SWZ(g, r) ((((g) ^ (r) ^ ((r) >> 3))) & 31)

typedef unsigned long long u64t;
__device__ __forceinline__ void fma2(u64t& acc, u64t a, u64t b) {
    asm("fma.rn.f32x2 %0, %1, %2, %0;" : "+l"(acc) : "l"(a), "l"(b));
}
__device__ __forceinline__ u64t bc2(float x) {
    u64t r; unsigned int xi = __float_as_uint(x);
    asm("mov.b64 %0, {%1, %1};" : "=l"(r) : "r"(xi));
    return r;
}
__device__ __forceinline__ float2 up2(u64t v) {
    float2 r; asm("mov.b64 {%0, %1}, %2;" : "=f"(r.x), "=f"(r.y) : "l"(v));
    return r;
}

// ---------------------------------------------------------------------------
// Kernel 1: entity FFNs + K/V/Q projections. Fused K+V pass (8tok x 4d x2).
// smem 69.1KB -> occ 3.
// ---------------------------------------------------------------------------
__global__ void __launch_bounds__(256, 3) encode_kernel(
    const float* __restrict__ pred_state, const float* __restrict__ prey_state,
    const float* __restrict__ obst_state, const float* __restrict__ emb,
    const float* __restrict__ p_w1, const float* __restrict__ p_b1,
    const float* __restrict__ p_w2, const float* __restrict__ p_b2,
    const float* __restrict__ y_w1, const float* __restrict__ y_b1,
    const float* __restrict__ y_w2, const float* __restrict__ y_b2,
    const float* __restrict__ o_w1, const float* __restrict__ o_b1,
    const float* __restrict__ o_w2, const float* __restrict__ o_b2,
    const float* __restrict__ wq, const float* __restrict__ bq,
    const float* __restrict__ wk, const float* __restrict__ bk,
    const float* __restrict__ wv, const float* __restrict__ bv)
{
    extern __shared__ float sm[];
    float* sW  = sm;            // 8192: W2@0 (X phase); then WK@0 + WV@4096; then WQ@0
    float* sX  = sm + 8192;     // 8192: H half then X swizzled
    float* sC  = sm + 16384;
    float* sBK = sm + 16448;
    float* sBV = sm + 16512;
    float* sBQ = sm + 16576;
    float* sB1 = sm + 16640;
    float* sW1 = sm + 16704;    // 192
    float* sSt = sm + 16896;    // 384 (total 17280)

    const int tid = threadIdx.x;
    const int blk = blockIdx.x;

    int type, inDim, perShift, slotBase, tok0;
    const float *state, *w1, *b1, *w2, *b2;
    if (blk < 256)       { type = 0; tok0 = blk * 128;          state = pred_state; w1 = p_w1; b1 = p_b1; w2 = p_w2; b2 = p_b2; inDim = 2; perShift = 4; slotBase = 0;   }
    else if (blk < 2304) { type = 1; tok0 = (blk - 256)  * 128; state = prey_state; w1 = y_w1; b1 = y_b1; w2 = y_w2; b2 = y_b2; inDim = 2; perShift = 7; slotBase = 16;  }
    else                 { type = 2; tok0 = (blk - 2304) * 128; state = obst_state; w1 = o_w1; b1 = o_b1; w2 = o_w2; b2 = o_b2; inDim = 3; perShift = 5; slotBase = 144; }

    for (int i = tid; i < 4096; i += 256) sW[i] = w2[i];
    if (tid < 64) {
        sC[tid]  = b2[tid] + emb[type * 64 + tid];
        sBK[tid] = bk[tid]; sBV[tid] = bv[tid]; sBQ[tid] = bq[tid]; sB1[tid] = b1[tid];
    }
    if (tid < inDim * 64) sW1[tid] = w1[tid];
    for (int i = tid; i < 128 * inDim; i += 256) {
        int t = i / inDim, j = i - t * inDim;
        sSt[t * 3 + j] = state[(tok0 + t) * inDim + j];
    }
    __syncthreads();

    const int dg = tid & 7, tg = tid >> 3, ds = dg * 8;

    // X = H @ W2 over two 32-k halves (H in sX low half)
    u64t accX[4][4];
#pragma unroll
    for (int i = 0; i < 4; i++)
#pragma unroll
        for (int j = 0; j < 4; j++) accX[i][j] = 0ULL;

#pragma unroll 1
    for (int h = 0; h < 2; h++) {
        for (int e = tid; e < 4096; e += 256) {
            int k = e >> 7, t = e & 127;
            int gk = h * 32 + k;
            float a = sB1[gk];
            for (int j = 0; j < inDim; j++) a += sSt[t * 3 + j] * sW1[j * 64 + gk];
            sX[k * 128 + t] = fmaxf(a, 0.f);
        }
        __syncthreads();
#pragma unroll 4
        for (int kk = 0; kk < 32; kk++) {
            float4 a4 = *(const float4*)(sX + kk * 128 + tg * 4);
            const float* wr = sW + (h * 32 + kk) * 64 + ds;
            ulonglong2 w01 = *(const ulonglong2*)(wr);
            ulonglong2 w23 = *(const ulonglong2*)(wr + 4);
            u64t bw[4] = {w01.x, w01.y, w23.x, w23.y};
            u64t av[4] = {bc2(a4.x), bc2(a4.y), bc2(a4.z), bc2(a4.w)};
#pragma unroll
            for (int i = 0; i < 4; i++)
#pragma unroll
                for (int j = 0; j < 4; j++) fma2(accX[i][j], av[i], bw[j]);
        }
        __syncthreads();
    }

    // write X swizzled; stage WK@0 + WV@4096
#pragma unroll
    for (int j2 = 0; j2 < 4; j2++) {
        int d0 = ds + 2 * j2, d1 = d0 + 1;
        float c0 = sC[d0], c1 = sC[d1];
        float2 u0 = up2(accX[0][j2]), u1 = up2(accX[1][j2]);
        float2 u2 = up2(accX[2][j2]), u3 = up2(accX[3][j2]);
        *(float4*)(sX + d0 * 128 + SWZ(tg, d0) * 4) =
            make_float4(u0.x + c0, u1.x + c0, u2.x + c0, u3.x + c0);
        *(float4*)(sX + d1 * 128 + SWZ(tg, d1) * 4) =
            make_float4(u0.y + c1, u1.y + c1, u2.y + c1, u3.y + c1);
    }
    for (int i = tid; i < 4096; i += 256) { sW[i] = wk[i]; sW[4096 + i] = wv[i]; }
    __syncthreads();

    // fused K+V pass: 8tok x 4d per thread, dual accumulators
    {
        const int tg16 = tid >> 4;      // 0..15 (8 tokens each)
        const int dgr  = tid & 15;      // 0..15 (4 d each)
        const int gT2   = tok0 + tg16 * 8;
        const int b2i   = gT2 >> perShift;
        const int lp2   = gT2 & ((1 << perShift) - 1);
        const int slot2 = slotBase + lp2;

        u64t aK[8][2], aV[8][2];
#pragma unroll
        for (int i = 0; i < 8; i++) {
            aK[i][0] = 0ULL; aK[i][1] = 0ULL;
            aV[i][0] = 0ULL; aV[i][1] = 0ULL;
        }
#pragma unroll 2
        for (int k = 0; k < 64; k++) {
            ulonglong2 kw = *(const ulonglong2*)(sW + k * 64 + dgr * 4);
            ulonglong2 vw = *(const ulonglong2*)(sW + 4096 + k * 64 + dgr * 4);
            float4 a0 = *(const float4*)(sX + k * 128 + SWZ(2 * tg16,     k) * 4);
            float4 a1 = *(const float4*)(sX + k * 128 + SWZ(2 * tg16 + 1, k) * 4);
            float af[8] = {a0.x, a0.y, a0.z, a0.w, a1.x, a1.y, a1.z, a1.w};
#pragma unroll
            for (int i = 0; i < 8; i++) {
                u64t ab = bc2(af[i]);
                fma2(aK[i][0], ab, kw.x);
                fma2(aK[i][1], ab, kw.y);
                fma2(aV[i][0], ab, vw.x);
                fma2(aV[i][1], ab, vw.y);
            }
        }
        // K stores: rows d = dgr*4 .. dgr*4+3, 8 consecutive slots each
#pragma unroll
        for (int j = 0; j < 2; j++) {
            int d0 = dgr * 4 + 2 * j, d1 = d0 + 1;
            float b0 = sBK[d0], b1v = sBK[d1];
            float2 p0 = up2(aK[0][j]), p1 = up2(aK[1][j]);
            float2 p2 = up2(aK[2][j]), p3 = up2(aK[3][j]);
            float2 p4 = up2(aK[4][j]), p5 = up2(aK[5][j]);
            float2 p6 = up2(aK[6][j]), p7 = up2(aK[7][j]);
            float* r0 = g_KT + (b2i * 64 + d0) * 176 + slot2;
            float* r1 = g_KT + (b2i * 64 + d1) * 176 + slot2;
            *(float4*)(r0)     = make_float4(p0.x + b0, p1.x + b0, p2.x + b0, p3.x + b0);
            *(float4*)(r0 + 4) = make_float4(p4.x + b0, p5.x + b0, p6.x + b0, p7.x + b0);
            *(float4*)(r1)     = make_float4(p0.y + b1v, p1.y + b1v, p2.y + b1v, p3.y + b1v);
            *(float4*)(r1 + 4) = make_float4(p4.y + b1v, p5.y + b1v, p6.y + b1v, p7.y + b1v);
        }
        // V stores: 8 token rows, 4 d each
        float vb0 = sBV[dgr * 4],     vb1 = sBV[dgr * 4 + 1];
        float vb2 = sBV[dgr * 4 + 2], vb3 = sBV[dgr * 4 + 3];
#pragma unroll
        for (int i = 0; i < 8; i++) {
            float2 v0 = up2(aV[i][0]), v1 = up2(aV[i][1]);
            *(float4*)(g_V + (b2i * 176 + slot2 + i) * 64 + dgr * 4) =
                make_float4(v0.x + vb0, v0.y + vb1, v1.x + vb2, v1.y + vb3);
        }
    }

    if (type == 1) {
        __syncthreads();
        for (int i = tid; i < 4096; i += 256) sW[i] = wq[i];
        __syncthreads();
        const int gT   = tok0 + tg * 4;
        const int b    = gT >> perShift;
        const int lp   = gT & ((1 << perShift) - 1);
        u64t aQ[4][4];
#pragma unroll
        for (int i = 0; i < 4; i++)
#pragma unroll
            for (int j = 0; j < 4; j++) aQ[i][j] = 0ULL;
#pragma unroll 4
        for (int k = 0; k < 64; k++) {
            float4 a4 = *(const float4*)(sX + k * 128 + SWZ(tg, k) * 4);
            const float* qr = sW + k * 64 + ds;
            ulonglong2 q01 = *(const ulonglong2*)(qr);
            ulonglong2 q23 = *(const ulonglong2*)(qr + 4);
            u64t qw[4] = {q01.x, q01.y, q23.x, q23.y};
            u64t av[4] = {bc2(a4.x), bc2(a4.y), bc2(a4.z), bc2(a4.w)};
#pragma unroll
            for (int i = 0; i < 4; i++)
#pragma unroll
                for (int j = 0; j < 4; j++) fma2(aQ[i][j], av[i], qw[j]);
        }
#pragma unroll
        for (int j2 = 0; j2 < 4; j2++) {
            int d0 = ds + 2 * j2, d1 = d0 + 1;
            float b0 = sBQ[d0], b1v = sBQ[d1];
            float2 u0 = up2(aQ[0][j2]), u1 = up2(aQ[1][j2]);
            float2 u2 = up2(aQ[2][j2]), u3 = up2(aQ[3][j2]);
            *(float4*)(g_QT + (b * 64 + d0) * 128 + lp) =
                make_float4(u0.x + b0, u1.x + b0, u2.x + b0, u3.x + b0);
            *(float4*)(g_QT + (b * 64 + d1) * 128 + lp) =
                make_float4(u0.y + b1v, u1.y + b1v, u2.y + b1v, u3.y + b1v);
        }
    }
}

// ---------------------------------------------------------------------------
// post-softmax helpers (unchanged 934us version). X buffers plain.
// ---------------------------------------------------------------------------
__device__ __forceinline__ void gemm48_plain(
    const float* __restrict__ A, const float* __restrict__ W,
    int qt, int dt, int k0, int klen, u64t acc[4][4])
{
#pragma unroll 4
    for (int kk = 0; kk < klen; kk++) {
        int k = k0 + kk;
        float4 a4 = *(const float4*)(A + k * 64 + (qt << 2));
        ulonglong2 w01 = *(const ulonglong2*)(W + k * 64 + dt * 8);
        ulonglong2 w23 = *(const ulonglong2*)(W + k * 64 + dt * 8 + 4);
        u64t wv4[4] = {w01.x, w01.y, w23.x, w23.y};
        u64t av[4] = {bc2(a4.x), bc2(a4.y), bc2(a4.z), bc2(a4.w)};
#pragma unroll
        for (int i = 0; i < 4; i++)
#pragma unroll
            for (int j = 0; j < 4; j++) fma2(acc[i][j], av[i], wv4[j]);
    }
}

__device__ __forceinline__ void gemm2_swz(
    const float* __restrict__ A, const float* __restrict__ W,
    int qt, int dt, int k0, int nblk, u64t acc[4][4])
{
#pragma unroll 1
    for (int blk = 0; blk < nblk; blk++) {
        const float* Ab = A + (k0 + blk * 16) * 64;
        const float* Wb = W + (k0 + blk * 16) * 64 + dt * 8;
#pragma unroll
        for (int kk = 0; kk < 16; kk++) {
            float4 a4 = *(const float4*)(Ab + kk * 64 + ((qt ^ kk) << 2));
            ulonglong2 w01 = *(const ulonglong2*)(Wb + kk * 64);
            ulonglong2 w23 = *(const ulonglong2*)(Wb + kk * 64 + 4);
            u64t wv4[4] = {w01.x, w01.y, w23.x, w23.y};
            u64t av[4] = {bc2(a4.x), bc2(a4.y), bc2(a4.z), bc2(a4.w)};
#pragma unroll
            for (int i = 0; i < 4; i++)
#pragma unroll
                for (int j = 0; j < 4; j++) fma2(acc[i][j], av[i], wv4[j]);
        }
    }
}

__device__ __forceinline__ float* scr_ptr(float* sS, float* sKV, int d, int off) {
    return (d < 48) ? (sS + 8192 + d * 64 + off) : (sKV + 8192 + (d - 48) * 64 + off);
}

__device__ __forceinline__ void store48(
    float* __restrict__ Out, int qt, int dt, u64t acc[4][4])
{
#pragma unroll
    for (int j = 0; j < 4; j++) {
        int d0 = dt * 8 + 2 * j, d1 = d0 + 1;
        float2 p0 = up2(acc[0][j]), p1 = up2(acc[1][j]);
        float2 p2 = up2(acc[2][j]), p3 = up2(acc[3][j]);
        *(float4*)(Out + d0 * 64 + (qt << 2)) = make_float4(p0.x, p1.x, p2.x, p3.x);
        *(float4*)(Out + d1 * 64 + (qt << 2)) = make_float4(p0.y, p1.y, p2.y, p3.y);
    }
}

__device__ __forceinline__ void store48_scr(
    float* sS, float* sKV, int qt, int dt, u64t acc[4][4])
{
#pragma unroll
    for (int j = 0; j < 4; j++) {
        int d0 = dt * 8 + 2 * j, d1 = d0 + 1;
        float2 p0 = up2(acc[0][j]), p1 = up2(acc[1][j]);
        float2 p2 = up2(acc[2][j]), p3 = up2(acc[3][j]);
        *(float4*)scr_ptr(sS, sKV, d0, qt << 2) = make_float4(p0.x, p1.x, p2.x, p3.x);
        *(float4*)scr_ptr(sS, sKV, d1, qt << 2) = make_float4(p0.y, p1.y, p2.y, p3.y);
    }
}

__device__ __forceinline__ void fin_head3(
    float* __restrict__ Out, float* sS, float* sKV,
    const float* __restrict__ bias,
    int qt, int dt, u64t acc[4][4], bool relu)
{
#pragma unroll
    for (int j = 0; j < 4; j++) {
        int d0 = dt * 8 + 2 * j, d1 = d0 + 1;
        float b0 = bias[d0], b1 = bias[d1];
        float* a0 = Out + d0 * 64 + (qt << 2);
        float* a1 = Out + d1 * 64 + (qt << 2);
        float4 o0 = *(float4*)a0, o1 = *(float4*)a1;
        float4 s0 = *(float4*)scr_ptr(sS, sKV, d0, qt << 2);
        float4 s1 = *(float4*)scr_ptr(sS, sKV, d1, qt << 2);
        float2 p0 = up2(acc[0][j]), p1 = up2(acc[1][j]);
        float2 p2 = up2(acc[2][j]), p3 = up2(acc[3][j]);
        o0.x += s0.x + p0.x + b0; o0.y += s0.y + p1.x + b0;
        o0.z += s0.z + p2.x + b0; o0.w += s0.w + p3.x + b0;
        o1.x += s1.x + p0.y + b1; o1.y += s1.y + p1.y + b1;
        o1.z += s1.z + p2.y + b1; o1.w += s1.w + p3.y + b1;
        if (relu) {
            o0.x = fmaxf(o0.x, 0.f); o0.y = fmaxf(o0.y, 0.f);
            o0.z = fmaxf(o0.z, 0.f); o0.w = fmaxf(o0.w, 0.f);
            o1.x = fmaxf(o1.x, 0.f); o1.y = fmaxf(o1.y, 0.f);
            o1.z = fmaxf(o1.z, 0.f); o1.w = fmaxf(o1.w, 0.f);
        }
        *(float4*)a0 = o0; *(float4*)a1 = o1;
    }
}

__device__ __forceinline__ void fin_pv48(
    float* __restrict__ Out, const float* __restrict__ sIv,
    int qt, int dt, u64t acc[4][4])
{
    float iv[4] = {sIv[qt * 4], sIv[qt * 4 + 1], sIv[qt * 4 + 2], sIv[qt * 4 + 3]};
#pragma unroll
    for (int j = 0; j < 4; j++) {
        int d0 = dt * 8 + 2 * j, d1 = d0 + 1;
        float* a0 = Out + d0 * 64 + (qt << 2);
        float* a1 = Out + d1 * 64 + (qt << 2);
        float4 o0 = *(float4*)a0, o1 = *(float4*)a1;
        float2 p0 = up2(acc[0][j]), p1 = up2(acc[1][j]);
        float2 p2 = up2(acc[2][j]), p3 = up2(acc[3][j]);
        o0.x = (o0.x + p0.x) * iv[0]; o0.y = (o0.y + p1.x) * iv[1];
        o0.z = (o0.z + p2.x) * iv[2]; o0.w = (o0.w + p3.x) * iv[3];
        o1.x = (o1.x + p0.y) * iv[0]; o1.y = (o1.y + p1.y) * iv[1];
        o1.z = (o1.z + p2.y) * iv[2]; o1.w = (o1.w + p3.y) * iv[3];
        *(float4*)a0 = o0; *(float4*)a1 = o1;
    }
}

// ---------------------------------------------------------------------------
// Kernel 2: attention + head (unchanged 934us version). 384 threads, occ 2.
// ---------------------------------------------------------------------------
__global__ void __launch_bounds__(384, 2) attn_kernel(
    const float* __restrict__ pred_state, const float* __restrict__ prey_state,
    const float* __restrict__ obst_state, const void* __restrict__ alive,
    const float* __restrict__ w_pos,
    const float* __restrict__ wo,   const float* __restrict__ bo,
    const float* __restrict__ n_w1, const float* __restrict__ n_b1,
    const float* __restrict__ n_w2, const float* __restrict__ n_b2,
    const float* __restrict__ n_w3, const float* __restrict__ n_b3,
    float* __restrict__ out)
{
    extern __shared__ float sm[];
    float* sKV = sm;
    float* sQT = sm + 12288;
    float* sS  = sm + 16384;
    float* sBK = sm + 27648;
    float* sMK = sm + 27824;
    float* sDQ = sm + 28000;
    float* sIv = sm + 28064;
    float* sBo = sm + 28128;
    float* sB1h= sm + 28192;
    float* sB2h= sm + 28256;
    float* sW3h= sm + 28320;
    float* sB3 = sm + 28384;
    __shared__ int sFl[2];

    const int tid = threadIdx.x;
    const int b   = blockIdx.x >> 1;
    const int qh  = (blockIdx.x & 1) << 6;

    if (tid == 0) { sFl[0] = 0; sFl[1] = 0; }
    __syncthreads();

    {
        const float4* gk = (const float4*)(g_KT + b * 11264);
        for (int i = tid; i < 2816; i += 384) {
            int d = i / 44, c = i - d * 44;
            *(float4*)(sKV + d * 192 + c * 4) = gk[i];
        }
        for (int i = tid; i < 1024; i += 384) {
            int d = i >> 4, c = i & 15;
            *(float4*)(sQT + d * 64 + c * 4) =
                *(const float4*)(g_QT + b * 8192 + d * 128 + qh + c * 4);
        }
        if (tid < 64) {
            sBo[tid] = bo[tid]; sB1h[tid] = n_b1[tid];
            sB2h[tid] = n_b2[tid]; sW3h[tid] = n_w3[tid];
        }
        if (tid == 0) sB3[0] = n_b3[0];
        if (tid < 128) {
            unsigned int v = ((const unsigned int*)alive)[tid];
            if (v == 0x3F800000u) atomicOr(&sFl[0], 1);
            else if (v > 1u)      atomicOr(&sFl[1], 1);
        }
    }
    __syncthreads();
    const int fmt = sFl[0] ? 2 : (sFl[1] ? 0 : 1);

    if (tid < NTOK) {
        int k = tid;
        float p0, p1, mk = 0.f;
        if (k < 16) {
            p0 = pred_state[(b * 16 + k) * 2];
            p1 = pred_state[(b * 16 + k) * 2 + 1];
        } else if (k < 144) {
            int j = k - 16;
            p0 = prey_state[(b * 128 + j) * 2];
            p1 = prey_state[(b * 128 + j) * 2 + 1];
            bool al;
            if (fmt == 0)      al = ((const unsigned char*)alive)[b * 128 + j] != 0;
            else if (fmt == 1) al = ((const int*)alive)[b * 128 + j] != 0;
            else               al = ((const float*)alive)[b * 128 + j] != 0.f;
            if (!al) mk = -1e9f;
        } else {
            int j = k - 144;
            p0 = obst_state[(b * 32 + j) * 3];
            p1 = obst_state[(b * 32 + j) * 3 + 1];
        }
        sBK[k] = p0 * w_pos[0] + p1 * w_pos[1];
        sMK[k] = mk;
    }
    if (tid >= 192 && tid < 256) {
        int q = qh + tid - 192;
        bool al;
        if (fmt == 0)      al = ((const unsigned char*)alive)[b * 128 + q] != 0;
        else if (fmt == 1) al = ((const int*)alive)[b * 128 + q] != 0;
        else               al = ((const float*)alive)[b * 128 + q] != 0.f;
        sDQ[tid - 192] = al ? 0.f : 1.f;
    }
    __syncthreads();

    if (tid < 352) {
        const int kg = tid >> 4, qg = tid & 15;
        u64t acc[4][4];
#pragma unroll
        for (int p = 0; p < 4; p++)
#pragma unroll
            for (int j = 0; j < 4; j++) acc[p][j] = 0ULL;
#pragma unroll 4
        for (int d = 0; d < 64; d++) {
            const float* kr = sKV + d * 192 + kg * 8;
            ulonglong2 kA = *(const ulonglong2*)(kr);
            ulonglong2 kB = *(const ulonglong2*)(kr + 4);
            float4 q4 = *(const float4*)(sQT + d * 64 + qg * 4);
            u64t kp[4] = {kA.x, kA.y, kB.x, kB.y};
            u64t qb[4] = {bc2(q4.x), bc2(q4.y), bc2(q4.z), bc2(q4.w)};
#pragma unroll
            for (int p = 0; p < 4; p++)
#pragma unroll
                for (int j = 0; j < 4; j++) fma2(acc[p][j], kp[p], qb[j]);
        }
        float dq[4] = {sDQ[qg * 4], sDQ[qg * 4 + 1], sDQ[qg * 4 + 2], sDQ[qg * 4 + 3]};
#pragma unroll
        for (int p = 0; p < 4; p++) {
            int r0 = kg * 8 + 2 * p, r1 = r0 + 1;
            float2 u0 = up2(acc[p][0]), u1 = up2(acc[p][1]);
            float2 u2 = up2(acc[p][2]), u3 = up2(acc[p][3]);
            float bk0 = sBK[r0], mk0 = sMK[r0];
            float bk1 = sBK[r1], mk1 = sMK[r1];
            *(float4*)(sS + r0 * 64 + ((qg ^ (r0 & 15)) << 2)) =
                make_float4((u0.x - bk0) * 0.125f + dq[0] * mk0,
                            (u1.x - bk0) * 0.125f + dq[1] * mk0,
                            (u2.x - bk0) * 0.125f + dq[2] * mk0,
                            (u3.x - bk0) * 0.125f + dq[3] * mk0);
            *(float4*)(sS + r1 * 64 + ((qg ^ (r1 & 15)) << 2)) =
                make_float4((u0.y - bk1) * 0.125f + dq[0] * mk1,
                            (u1.y - bk1) * 0.125f + dq[1] * mk1,
                            (u2.y - bk1) * 0.125f + dq[2] * mk1,
                            (u3.y - bk1) * 0.125f + dq[3] * mk1);
        }
    }
    __syncthreads();

    {
        const float4* gv = (const float4*)(g_V + b * 11264);
        float4* dv = (float4*)sKV;
        for (int i = tid; i < 2816; i += 384) dv[i] = gv[i];
    }
    if (tid < 256) {
        int q = tid >> 2, sub = tid & 3;
        int g = q >> 2, qr = q & 3;
        int k0 = sub * 44, k1 = k0 + 44;
        float m = -3.4e38f;
        for (int k = k0; k < k1; k++)
            m = fmaxf(m, sS[k * 64 + ((g ^ (k & 15)) << 2) + qr]);
        m = fmaxf(m, __shfl_xor_sync(0xFFFFFFFFu, m, 1));
        m = fmaxf(m, __shfl_xor_sync(0xFFFFFFFFu, m, 2));
        float ssum = 0.f;
        for (int k = k0; k < k1; k++) {
            int idx = k * 64 + ((g ^ (k & 15)) << 2) + qr;
            float p = __expf(sS[idx] - m);
            ssum += p;
            sS[idx] = p;
        }
        ssum += __shfl_xor_sync(0xFFFFFFFFu, ssum, 1);
        ssum += __shfl_xor_sync(0xFFFFFFFFu, ssum, 2);
        if (sub == 0) sIv[q] = 1.f / ssum;
    }
    __syncthreads();

    float* sX0  = sQT;
    float* sX1  = sKV;
    float* sWo  = sS;
    float* sW1h = sS + 4096;
    float* sW2h = sKV + 4096;
    u64t acc2[4][4];
#define ZACC2 \
    _Pragma("unroll") for (int i = 0; i < 4; i++) \
    _Pragma("unroll") for (int j = 0; j < 4; j++) acc2[i][j] = 0ULL;

    {
        const int qt = tid & 15, dt = (tid >> 4) & 7, half = (tid >> 7) & 1;
        ZACC2
        if (tid < 256) {
            gemm2_swz(sS, sKV, qt, dt, half * 96, half ? 5 : 6, acc2);
            if (half) store48(sX0, qt, dt, acc2);
        }
        __syncthreads();
        if (tid < 128) fin_pv48(sX0, sIv, qt, dt, acc2);
    }
    for (int i = tid; i < 4096; i += 384) {
        sWo[i]  = wo[i];
        sW1h[i] = n_w1[i];
        sW2h[i] = n_w2[i];
    }
    __syncthreads();

    const int t128 = tid & 127;
    const int hq = t128 & 15, hd = (t128 >> 4) & 7;
    const int chunk = tid >> 7;
    const int hk0 = (chunk == 0) ? 0 : (chunk == 1 ? 22 : 43);
    const int hkl = (chunk == 0) ? 22 : 21;

    ZACC2
    gemm48_plain(sX0, sWo, hq, hd, hk0, hkl, acc2);
    if (chunk == 1) store48(sX1, hq, hd, acc2);
    else if (chunk == 2) store48_scr(sS, sKV, hq, hd, acc2);
    __syncthreads();
    if (chunk == 0) fin_head3(sX1, sS, sKV, sBo, hq, hd, acc2, false);
    __syncthreads();

    ZACC2
    gemm48_plain(sX1, sW1h, hq, hd, hk0, hkl, acc2);
    if (chunk == 1) store48(sX0, hq, hd, acc2);
    else if (chunk == 2) store48_scr(sS, sKV, hq, hd, acc2);
    __syncthreads();
    if (chunk == 0) fin_head3(sX0, sS, sKV, sB1h, hq, hd, acc2, true);
    __syncthreads();

    ZACC2
    gemm48_plain(sX0, sW2h, hq, hd, hk0, hkl, acc2);
    if (chunk == 1) store48(sX1, hq, hd, acc2);
    else if (chunk == 2) store48_scr(sS, sKV, hq, hd, acc2);
    __syncthreads();
    if (chunk == 0) fin_head3(sX1, sS, sKV, sB2h, hq, hd, acc2, true);
    __syncthreads();

    if (tid < 256) {
        int q = tid >> 2, sub = tid & 3;
        float a = 0.f;
#pragma unroll 4
        for (int dd = 0; dd < 16; dd++) {
            int d = sub * 16 + dd;
            a += sX1[d * 64 + q] * sW3h[d];
        }
        a += __shfl_xor_sync(0xFFFFFFFFu, a, 1);
        a += __shfl_xor_sync(0xFFFFFFFFu, a, 2);
        if (sub == 0) out[b * 128 + qh + q] = tanhf(a + sB3[0]);
    }
}

// ---------------------------------------------------------------------------
extern "C" void kernel_launch(void* const* d_in, const int* in_sizes, int n_in,
                              void* d_out, int out_size)
{
    const float* pred  = (const float*)d_in[0];
    const float* prey  = (const float*)d_in[1];
    const float* obst  = (const float*)d_in[2];
    const void*  alive = d_in[3];
    const float* emb   = (const float*)d_in[4];
    const float* p_w1 = (const float*)d_in[5],  *p_b1 = (const float*)d_in[6];
    const float* p_w2 = (const float*)d_in[7],  *p_b2 = (const float*)d_in[8];
    const float* y_w1 = (const float*)d_in[9],  *y_b1 = (const float*)d_in[10];
    const float* y_w2 = (const float*)d_in[11], *y_b2 = (const float*)d_in[12];
    const float* o_w1 = (const float*)d_in[13], *o_b1 = (const float*)d_in[14];
    const float* o_w2 = (const float*)d_in[15], *o_b2 = (const float*)d_in[16];
    const float* wq = (const float*)d_in[17], *bq = (const float*)d_in[18];
    const float* wk = (const float*)d_in[19], *bk = (const float*)d_in[20];
    const float* wv = (const float*)d_in[21], *bv = (const float*)d_in[22];
    const float* wo = (const float*)d_in[23], *bo = (const float*)d_in[24];
    const float* w_pos = (const float*)d_in[25];
    const float* n_w1 = (const float*)d_in[26], *n_b1 = (const float*)d_in[27];
    const float* n_w2 = (const float*)d_in[28], *n_b2 = (const float*)d_in[29];
    const float* n_w3 = (const float*)d_in[30], *n_b3 = (const float*)d_in[31];
    float* out = (float*)d_out;

    cudaFuncSetAttribute(encode_kernel, cudaFuncAttributeMaxDynamicSharedMemorySize, 17280 * 4);
    cudaFuncSetAttribute(attn_kernel,   cudaFuncAttributeMaxDynamicSharedMemorySize, 28416 * 4);

    encode_kernel<<<2816, 256, 17280 * 4>>>(pred, prey, obst, emb,
        p_w1, p_b1, p_w2, p_b2, y_w1, y_b1, y_w2, y_b2, o_w1, o_b1, o_w2, o_b2,
        wq, bq, wk, bk, wv, bv);
    attn_kernel<<<4096, 384, 28416 * 4>>>(pred, prey, obst, alive, w_pos,
        wo, bo, n_w1, n_b1, n_w2, n_b2, n_w3, n_b3, out);
}

// round 16
// speedup vs baseline: 1.1432x; 1.1432x over previous
#include <cuda_runtime.h>
#include <math.h>

#define NTOK 176

__device__ float g_KT[2048 * 64 * 176];
__device__ float g_V [2048 * 176 * 64];
__device__ float g_QT[2048 * 64 * 128];

#define SWZ(g, r) ((((g) ^ (r) ^ ((r) >> 3))) & 31)

typedef unsigned long long u64t;
__device__ __forceinline__ void fma2(u64t& acc, u64t a, u64t b) {
    asm("fma.rn.f32x2 %0, %1, %2, %0;" : "+l"(acc) : "l"(a), "l"(b));
}
__device__ __forceinline__ u64t bc2(float x) {
    u64t r; unsigned int xi = __float_as_uint(x);
    asm("mov.b64 %0, {%1, %1};" : "=l"(r) : "r"(xi));
    return r;
}
__device__ __forceinline__ float2 up2(u64t v) {
    float2 r; asm("mov.b64 {%0, %1}, %2;" : "=f"(r.x), "=f"(r.y) : "l"(v));
    return r;
}

// ---------------------------------------------------------------------------
// Kernel 1: entity FFNs + K/V/Q projections (R14 structure, occ 4).
// Weight staging vectorized to float4.
// ---------------------------------------------------------------------------
__global__ void __launch_bounds__(256, 4) encode_kernel(
    const float* __restrict__ pred_state, const float* __restrict__ prey_state,
    const float* __restrict__ obst_state, const float* __restrict__ emb,
    const float* __restrict__ p_w1, const float* __restrict__ p_b1,
    const float* __restrict__ p_w2, const float* __restrict__ p_b2,
    const float* __restrict__ y_w1, const float* __restrict__ y_b1,
    const float* __restrict__ y_w2, const float* __restrict__ y_b2,
    const float* __restrict__ o_w1, const float* __restrict__ o_b1,
    const float* __restrict__ o_w2, const float* __restrict__ o_b2,
    const float* __restrict__ wq, const float* __restrict__ bq,
    const float* __restrict__ wk, const float* __restrict__ bk,
    const float* __restrict__ wv, const float* __restrict__ bv)
{
    extern __shared__ float sm[];
    float* sW  = sm;
    float* sX  = sm + 4096;
    float* sC  = sm + 12288;
    float* sBK = sm + 12352;
    float* sBV = sm + 12416;
    float* sBQ = sm + 12480;
    float* sB1 = sm + 12544;
    float* sW1 = sm + 12608;
    float* sSt = sm + 12800;

    const int tid = threadIdx.x;
    const int blk = blockIdx.x;

    int type, inDim, perShift, slotBase, tok0;
    const float *state, *w1, *b1, *w2, *b2;
    if (blk < 256)       { type = 0; tok0 = blk * 128;          state = pred_state; w1 = p_w1; b1 = p_b1; w2 = p_w2; b2 = p_b2; inDim = 2; perShift = 4; slotBase = 0;   }
    else if (blk < 2304) { type = 1; tok0 = (blk - 256)  * 128; state = prey_state; w1 = y_w1; b1 = y_b1; w2 = y_w2; b2 = y_b2; inDim = 2; perShift = 7; slotBase = 16;  }
    else                 { type = 2; tok0 = (blk - 2304) * 128; state = obst_state; w1 = o_w1; b1 = o_b1; w2 = o_w2; b2 = o_b2; inDim = 3; perShift = 5; slotBase = 144; }

    for (int i = tid; i < 1024; i += 256)
        ((float4*)sW)[i] = ((const float4*)w2)[i];
    if (tid < 64) {
        sC[tid]  = b2[tid] + emb[type * 64 + tid];
        sBK[tid] = bk[tid]; sBV[tid] = bv[tid]; sBQ[tid] = bq[tid]; sB1[tid] = b1[tid];
    }
    if (tid < inDim * 64) sW1[tid] = w1[tid];
    for (int i = tid; i < 128 * inDim; i += 256) {
        int t = i / inDim, j = i - t * inDim;
        sSt[t * 3 + j] = state[(tok0 + t) * inDim + j];
    }
    __syncthreads();

    const int dg = tid & 7, tg = tid >> 3, ds = dg * 8;

    u64t accX[4][4];
#pragma unroll
    for (int i = 0; i < 4; i++)
#pragma unroll
        for (int j = 0; j < 4; j++) accX[i][j] = 0ULL;

#pragma unroll 1
    for (int h = 0; h < 2; h++) {
        for (int e = tid; e < 4096; e += 256) {
            int k = e >> 7, t = e & 127;
            int gk = h * 32 + k;
            float a = sB1[gk];
            for (int j = 0; j < inDim; j++) a += sSt[t * 3 + j] * sW1[j * 64 + gk];
            sX[k * 128 + t] = fmaxf(a, 0.f);
        }
        __syncthreads();
#pragma unroll 4
        for (int kk = 0; kk < 32; kk++) {
            float4 a4 = *(const float4*)(sX + kk * 128 + tg * 4);
            const float* wr = sW + (h * 32 + kk) * 64 + ds;
            ulonglong2 w01 = *(const ulonglong2*)(wr);
            ulonglong2 w23 = *(const ulonglong2*)(wr + 4);
            u64t bw[4] = {w01.x, w01.y, w23.x, w23.y};
            u64t av[4] = {bc2(a4.x), bc2(a4.y), bc2(a4.z), bc2(a4.w)};
#pragma unroll
            for (int i = 0; i < 4; i++)
#pragma unroll
                for (int j = 0; j < 4; j++) fma2(accX[i][j], av[i], bw[j]);
        }
        __syncthreads();
    }

#pragma unroll
    for (int j2 = 0; j2 < 4; j2++) {
        int d0 = ds + 2 * j2, d1 = d0 + 1;
        float c0 = sC[d0], c1 = sC[d1];
        float2 u0 = up2(accX[0][j2]), u1 = up2(accX[1][j2]);
        float2 u2 = up2(accX[2][j2]), u3 = up2(accX[3][j2]);
        *(float4*)(sX + d0 * 128 + SWZ(tg, d0) * 4) =
            make_float4(u0.x + c0, u1.x + c0, u2.x + c0, u3.x + c0);
        *(float4*)(sX + d1 * 128 + SWZ(tg, d1) * 4) =
            make_float4(u0.y + c1, u1.y + c1, u2.y + c1, u3.y + c1);
    }
    for (int i = tid; i < 1024; i += 256)
        ((float4*)sW)[i] = ((const float4*)wk)[i];
    __syncthreads();

    const int gT   = tok0 + tg * 4;
    const int b    = gT >> perShift;
    const int lp   = gT & ((1 << perShift) - 1);
    const int slot = slotBase + lp;

    {
        u64t aK[4][4];
#pragma unroll
        for (int i = 0; i < 4; i++)
#pragma unroll
            for (int j = 0; j < 4; j++) aK[i][j] = 0ULL;
#pragma unroll 4
        for (int k = 0; k < 64; k++) {
            float4 a4 = *(const float4*)(sX + k * 128 + SWZ(tg, k) * 4);
            const float* kr = sW + k * 64 + ds;
            ulonglong2 k01 = *(const ulonglong2*)(kr);
            ulonglong2 k23 = *(const ulonglong2*)(kr + 4);
            u64t kw[4] = {k01.x, k01.y, k23.x, k23.y};
            u64t av[4] = {bc2(a4.x), bc2(a4.y), bc2(a4.z), bc2(a4.w)};
#pragma unroll
            for (int i = 0; i < 4; i++)
#pragma unroll
                for (int j = 0; j < 4; j++) fma2(aK[i][j], av[i], kw[j]);
        }
#pragma unroll
        for (int j2 = 0; j2 < 4; j2++) {
            int d0 = ds + 2 * j2, d1 = d0 + 1;
            float b0 = sBK[d0], b1v = sBK[d1];
            float2 u0 = up2(aK[0][j2]), u1 = up2(aK[1][j2]);
            float2 u2 = up2(aK[2][j2]), u3 = up2(aK[3][j2]);
            *(float4*)(g_KT + (b * 64 + d0) * 176 + slot) =
                make_float4(u0.x + b0, u1.x + b0, u2.x + b0, u3.x + b0);
            *(float4*)(g_KT + (b * 64 + d1) * 176 + slot) =
                make_float4(u0.y + b1v, u1.y + b1v, u2.y + b1v, u3.y + b1v);
        }
    }
    __syncthreads();
    for (int i = tid; i < 1024; i += 256)
        ((float4*)sW)[i] = ((const float4*)wv)[i];
    __syncthreads();

    {
        u64t aV[4][4];
#pragma unroll
        for (int i = 0; i < 4; i++)
#pragma unroll
            for (int j = 0; j < 4; j++) aV[i][j] = 0ULL;
#pragma unroll 4
        for (int k = 0; k < 64; k++) {
            float4 a4 = *(const float4*)(sX + k * 128 + SWZ(tg, k) * 4);
            const float* vr = sW + k * 64 + ds;
            ulonglong2 v01 = *(const ulonglong2*)(vr);
            ulonglong2 v23 = *(const ulonglong2*)(vr + 4);
            u64t vw[4] = {v01.x, v01.y, v23.x, v23.y};
            u64t av[4] = {bc2(a4.x), bc2(a4.y), bc2(a4.z), bc2(a4.w)};
#pragma unroll
            for (int i = 0; i < 4; i++)
#pragma unroll
                for (int j = 0; j < 4; j++) fma2(aV[i][j], av[i], vw[j]);
        }
#pragma unroll
        for (int i = 0; i < 4; i++) {
            int row = (b * 176 + slot + i) * 64;
            float2 v0 = up2(aV[i][0]), v1 = up2(aV[i][1]);
            float2 v2 = up2(aV[i][2]), v3 = up2(aV[i][3]);
            *(float4*)(g_V + row + ds) =
                make_float4(v0.x + sBV[ds], v0.y + sBV[ds + 1], v1.x + sBV[ds + 2], v1.y + sBV[ds + 3]);
            *(float4*)(g_V + row + ds + 4) =
                make_float4(v2.x + sBV[ds + 4], v2.y + sBV[ds + 5], v3.x + sBV[ds + 6], v3.y + sBV[ds + 7]);
        }
    }

    if (type == 1) {
        __syncthreads();
        for (int i = tid; i < 1024; i += 256)
            ((float4*)sW)[i] = ((const float4*)wq)[i];
        __syncthreads();
        u64t aQ[4][4];
#pragma unroll
        for (int i = 0; i < 4; i++)
#pragma unroll
            for (int j = 0; j < 4; j++) aQ[i][j] = 0ULL;
#pragma unroll 4
        for (int k = 0; k < 64; k++) {
            float4 a4 = *(const float4*)(sX + k * 128 + SWZ(tg, k) * 4);
            const float* qr = sW + k * 64 + ds;
            ulonglong2 q01 = *(const ulonglong2*)(qr);
            ulonglong2 q23 = *(const ulonglong2*)(qr + 4);
            u64t qw[4] = {q01.x, q01.y, q23.x, q23.y};
            u64t av[4] = {bc2(a4.x), bc2(a4.y), bc2(a4.z), bc2(a4.w)};
#pragma unroll
            for (int i = 0; i < 4; i++)
#pragma unroll
                for (int j = 0; j < 4; j++) fma2(aQ[i][j], av[i], qw[j]);
        }
#pragma unroll
        for (int j2 = 0; j2 < 4; j2++) {
            int d0 = ds + 2 * j2, d1 = d0 + 1;
            float b0 = sBQ[d0], b1v = sBQ[d1];
            float2 u0 = up2(aQ[0][j2]), u1 = up2(aQ[1][j2]);
            float2 u2 = up2(aQ[2][j2]), u3 = up2(aQ[3][j2]);
            *(float4*)(g_QT + (b * 64 + d0) * 128 + lp) =
                make_float4(u0.x + b0, u1.x + b0, u2.x + b0, u3.x + b0);
            *(float4*)(g_QT + (b * 64 + d1) * 128 + lp) =
                make_float4(u0.y + b1v, u1.y + b1v, u2.y + b1v, u3.y + b1v);
        }
    }
}

// ---------------------------------------------------------------------------
// post-softmax helpers (unchanged 934us version). X buffers plain.
// ---------------------------------------------------------------------------
__device__ __forceinline__ void gemm48_plain(
    const float* __restrict__ A, const float* __restrict__ W,
    int qt, int dt, int k0, int klen, u64t acc[4][4])
{
#pragma unroll 4
    for (int kk = 0; kk < klen; kk++) {
        int k = k0 + kk;
        float4 a4 = *(const float4*)(A + k * 64 + (qt << 2));
        ulonglong2 w01 = *(const ulonglong2*)(W + k * 64 + dt * 8);
        ulonglong2 w23 = *(const ulonglong2*)(W + k * 64 + dt * 8 + 4);
        u64t wv4[4] = {w01.x, w01.y, w23.x, w23.y};
        u64t av[4] = {bc2(a4.x), bc2(a4.y), bc2(a4.z), bc2(a4.w)};
#pragma unroll
        for (int i = 0; i < 4; i++)
#pragma unroll
            for (int j = 0; j < 4; j++) fma2(acc[i][j], av[i], wv4[j]);
    }
}

__device__ __forceinline__ void gemm2_swz(
    const float* __restrict__ A, const float* __restrict__ W,
    int qt, int dt, int k0, int nblk, u64t acc[4][4])
{
#pragma unroll 1
    for (int blk = 0; blk < nblk; blk++) {
        const float* Ab = A + (k0 + blk * 16) * 64;
        const float* Wb = W + (k0 + blk * 16) * 64 + dt * 8;
#pragma unroll
        for (int kk = 0; kk < 16; kk++) {
            float4 a4 = *(const float4*)(Ab + kk * 64 + ((qt ^ kk) << 2));
            ulonglong2 w01 = *(const ulonglong2*)(Wb + kk * 64);
            ulonglong2 w23 = *(const ulonglong2*)(Wb + kk * 64 + 4);
            u64t wv4[4] = {w01.x, w01.y, w23.x, w23.y};
            u64t av[4] = {bc2(a4.x), bc2(a4.y), bc2(a4.z), bc2(a4.w)};
#pragma unroll
            for (int i = 0; i < 4; i++)
#pragma unroll
                for (int j = 0; j < 4; j++) fma2(acc[i][j], av[i], wv4[j]);
        }
    }
}

__device__ __forceinline__ float* scr_ptr(float* sS, float* sKV, int d, int off) {
    return (d < 48) ? (sS + 8192 + d * 64 + off) : (sKV + 8192 + (d - 48) * 64 + off);
}

__device__ __forceinline__ void store48(
    float* __restrict__ Out, int qt, int dt, u64t acc[4][4])
{
#pragma unroll
    for (int j = 0; j < 4; j++) {
        int d0 = dt * 8 + 2 * j, d1 = d0 + 1;
        float2 p0 = up2(acc[0][j]), p1 = up2(acc[1][j]);
        float2 p2 = up2(acc[2][j]), p3 = up2(acc[3][j]);
        *(float4*)(Out + d0 * 64 + (qt << 2)) = make_float4(p0.x, p1.x, p2.x, p3.x);
        *(float4*)(Out + d1 * 64 + (qt << 2)) = make_float4(p0.y, p1.y, p2.y, p3.y);
    }
}

__device__ __forceinline__ void store48_scr(
    float* sS, float* sKV, int qt, int dt, u64t acc[4][4])
{
#pragma unroll
    for (int j = 0; j < 4; j++) {
        int d0 = dt * 8 + 2 * j, d1 = d0 + 1;
        float2 p0 = up2(acc[0][j]), p1 = up2(acc[1][j]);
        float2 p2 = up2(acc[2][j]), p3 = up2(acc[3][j]);
        *(float4*)scr_ptr(sS, sKV, d0, qt << 2) = make_float4(p0.x, p1.x, p2.x, p3.x);
        *(float4*)scr_ptr(sS, sKV, d1, qt << 2) = make_float4(p0.y, p1.y, p2.y, p3.y);
    }
}

__device__ __forceinline__ void fin_head3(
    float* __restrict__ Out, float* sS, float* sKV,
    const float* __restrict__ bias,
    int qt, int dt, u64t acc[4][4], bool relu)
{
#pragma unroll
    for (int j = 0; j < 4; j++) {
        int d0 = dt * 8 + 2 * j, d1 = d0 + 1;
        float b0 = bias[d0], b1 = bias[d1];
        float* a0 = Out + d0 * 64 + (qt << 2);
        float* a1 = Out + d1 * 64 + (qt << 2);
        float4 o0 = *(float4*)a0, o1 = *(float4*)a1;
        float4 s0 = *(float4*)scr_ptr(sS, sKV, d0, qt << 2);
        float4 s1 = *(float4*)scr_ptr(sS, sKV, d1, qt << 2);
        float2 p0 = up2(acc[0][j]), p1 = up2(acc[1][j]);
        float2 p2 = up2(acc[2][j]), p3 = up2(acc[3][j]);
        o0.x += s0.x + p0.x + b0; o0.y += s0.y + p1.x + b0;
        o0.z += s0.z + p2.x + b0; o0.w += s0.w + p3.x + b0;
        o1.x += s1.x + p0.y + b1; o1.y += s1.y + p1.y + b1;
        o1.z += s1.z + p2.y + b1; o1.w += s1.w + p3.y + b1;
        if (relu) {
            o0.x = fmaxf(o0.x, 0.f); o0.y = fmaxf(o0.y, 0.f);
            o0.z = fmaxf(o0.z, 0.f); o0.w = fmaxf(o0.w, 0.f);
            o1.x = fmaxf(o1.x, 0.f); o1.y = fmaxf(o1.y, 0.f);
            o1.z = fmaxf(o1.z, 0.f); o1.w = fmaxf(o1.w, 0.f);
        }
        *(float4*)a0 = o0; *(float4*)a1 = o1;
    }
}

__device__ __forceinline__ void fin_pv48(
    float* __restrict__ Out, const float* __restrict__ sIv,
    int qt, int dt, u64t acc[4][4])
{
    float iv[4] = {sIv[qt * 4], sIv[qt * 4 + 1], sIv[qt * 4 + 2], sIv[qt * 4 + 3]};
#pragma unroll
    for (int j = 0; j < 4; j++) {
        int d0 = dt * 8 + 2 * j, d1 = d0 + 1;
        float* a0 = Out + d0 * 64 + (qt << 2);
        float* a1 = Out + d1 * 64 + (qt << 2);
        float4 o0 = *(float4*)a0, o1 = *(float4*)a1;
        float2 p0 = up2(acc[0][j]), p1 = up2(acc[1][j]);
        float2 p2 = up2(acc[2][j]), p3 = up2(acc[3][j]);
        o0.x = (o0.x + p0.x) * iv[0]; o0.y = (o0.y + p1.x) * iv[1];
        o0.z = (o0.z + p2.x) * iv[2]; o0.w = (o0.w + p3.x) * iv[3];
        o1.x = (o1.x + p0.y) * iv[0]; o1.y = (o1.y + p1.y) * iv[1];
        o1.z = (o1.z + p2.y) * iv[2]; o1.w = (o1.w + p3.y) * iv[3];
        *(float4*)a0 = o0; *(float4*)a1 = o1;
    }
}

// ---------------------------------------------------------------------------
// Kernel 2: attention + head (934us version; weight staging vectorized).
// ---------------------------------------------------------------------------
__global__ void __launch_bounds__(384, 2) attn_kernel(
    const float* __restrict__ pred_state, const float* __restrict__ prey_state,
    const float* __restrict__ obst_state, const void* __restrict__ alive,
    const float* __restrict__ w_pos,
    const float* __restrict__ wo,   const float* __restrict__ bo,
    const float* __restrict__ n_w1, const float* __restrict__ n_b1,
    const float* __restrict__ n_w2, const float* __restrict__ n_b2,
    const float* __restrict__ n_w3, const float* __restrict__ n_b3,
    float* __restrict__ out)
{
    extern __shared__ float sm[];
    float* sKV = sm;
    float* sQT = sm + 12288;
    float* sS  = sm + 16384;
    float* sBK = sm + 27648;
    float* sMK = sm + 27824;
    float* sDQ = sm + 28000;
    float* sIv = sm + 28064;
    float* sBo = sm + 28128;
    float* sB1h= sm + 28192;
    float* sB2h= sm + 28256;
    float* sW3h= sm + 28320;
    float* sB3 = sm + 28384;
    __shared__ int sFl[2];

    const int tid = threadIdx.x;
    const int b   = blockIdx.x >> 1;
    const int qh  = (blockIdx.x & 1) << 6;

    if (tid == 0) { sFl[0] = 0; sFl[1] = 0; }
    __syncthreads();

    {
        const float4* gk = (const float4*)(g_KT + b * 11264);
        for (int i = tid; i < 2816; i += 384) {
            int d = i / 44, c = i - d * 44;
            *(float4*)(sKV + d * 192 + c * 4) = gk[i];
        }
        for (int i = tid; i < 1024; i += 384) {
            int d = i >> 4, c = i & 15;
            *(float4*)(sQT + d * 64 + c * 4) =
                *(const float4*)(g_QT + b * 8192 + d * 128 + qh + c * 4);
        }
        if (tid < 64) {
            sBo[tid] = bo[tid]; sB1h[tid] = n_b1[tid];
            sB2h[tid] = n_b2[tid]; sW3h[tid] = n_w3[tid];
        }
        if (tid == 0) sB3[0] = n_b3[0];
        if (tid < 128) {
            unsigned int v = ((const unsigned int*)alive)[tid];
            if (v == 0x3F800000u) atomicOr(&sFl[0], 1);
            else if (v > 1u)      atomicOr(&sFl[1], 1);
        }
    }
    __syncthreads();
    const int fmt = sFl[0] ? 2 : (sFl[1] ? 0 : 1);

    if (tid < NTOK) {
        int k = tid;
        float p0, p1, mk = 0.f;
        if (k < 16) {
            p0 = pred_state[(b * 16 + k) * 2];
            p1 = pred_state[(b * 16 + k) * 2 + 1];
        } else if (k < 144) {
            int j = k - 16;
            p0 = prey_state[(b * 128 + j) * 2];
            p1 = prey_state[(b * 128 + j) * 2 + 1];
            bool al;
            if (fmt == 0)      al = ((const unsigned char*)alive)[b * 128 + j] != 0;
            else if (fmt == 1) al = ((const int*)alive)[b * 128 + j] != 0;
            else               al = ((const float*)alive)[b * 128 + j] != 0.f;
            if (!al) mk = -1e9f;
        } else {
            int j = k - 144;
            p0 = obst_state[(b * 32 + j) * 3];
            p1 = obst_state[(b * 32 + j) * 3 + 1];
        }
        sBK[k] = p0 * w_pos[0] + p1 * w_pos[1];
        sMK[k] = mk;
    }
    if (tid >= 192 && tid < 256) {
        int q = qh + tid - 192;
        bool al;
        if (fmt == 0)      al = ((const unsigned char*)alive)[b * 128 + q] != 0;
        else if (fmt == 1) al = ((const int*)alive)[b * 128 + q] != 0;
        else               al = ((const float*)alive)[b * 128 + q] != 0.f;
        sDQ[tid - 192] = al ? 0.f : 1.f;
    }
    __syncthreads();

    if (tid < 352) {
        const int kg = tid >> 4, qg = tid & 15;
        u64t acc[4][4];
#pragma unroll
        for (int p = 0; p < 4; p++)
#pragma unroll
            for (int j = 0; j < 4; j++) acc[p][j] = 0ULL;
#pragma unroll 4
        for (int d = 0; d < 64; d++) {
            const float* kr = sKV + d * 192 + kg * 8;
            ulonglong2 kA = *(const ulonglong2*)(kr);
            ulonglong2 kB = *(const ulonglong2*)(kr + 4);
            float4 q4 = *(const float4*)(sQT + d * 64 + qg * 4);
            u64t kp[4] = {kA.x, kA.y, kB.x, kB.y};
            u64t qb[4] = {bc2(q4.x), bc2(q4.y), bc2(q4.z), bc2(q4.w)};
#pragma unroll
            for (int p = 0; p < 4; p++)
#pragma unroll
                for (int j = 0; j < 4; j++) fma2(acc[p][j], kp[p], qb[j]);
        }
        float dq[4] = {sDQ[qg * 4], sDQ[qg * 4 + 1], sDQ[qg * 4 + 2], sDQ[qg * 4 + 3]};
#pragma unroll
        for (int p = 0; p < 4; p++) {
            int r0 = kg * 8 + 2 * p, r1 = r0 + 1;
            float2 u0 = up2(acc[p][0]), u1 = up2(acc[p][1]);
            float2 u2 = up2(acc[p][2]), u3 = up2(acc[p][3]);
            float bk0 = sBK[r0], mk0 = sMK[r0];
            float bk1 = sBK[r1], mk1 = sMK[r1];
            *(float4*)(sS + r0 * 64 + ((qg ^ (r0 & 15)) << 2)) =
                make_float4((u0.x - bk0) * 0.125f + dq[0] * mk0,
                            (u1.x - bk0) * 0.125f + dq[1] * mk0,
                            (u2.x - bk0) * 0.125f + dq[2] * mk0,
                            (u3.x - bk0) * 0.125f + dq[3] * mk0);
            *(float4*)(sS + r1 * 64 + ((qg ^ (r1 & 15)) << 2)) =
                make_float4((u0.y - bk1) * 0.125f + dq[0] * mk1,
                            (u1.y - bk1) * 0.125f + dq[1] * mk1,
                            (u2.y - bk1) * 0.125f + dq[2] * mk1,
                            (u3.y - bk1) * 0.125f + dq[3] * mk1);
        }
    }
    __syncthreads();

    {
        const float4* gv = (const float4*)(g_V + b * 11264);
        float4* dv = (float4*)sKV;
        for (int i = tid; i < 2816; i += 384) dv[i] = gv[i];
    }
    if (tid < 256) {
        int q = tid >> 2, sub = tid & 3;
        int g = q >> 2, qr = q & 3;
        int k0 = sub * 44, k1 = k0 + 44;
        float m = -3.4e38f;
        for (int k = k0; k < k1; k++)
            m = fmaxf(m, sS[k * 64 + ((g ^ (k & 15)) << 2) + qr]);
        m = fmaxf(m, __shfl_xor_sync(0xFFFFFFFFu, m, 1));
        m = fmaxf(m, __shfl_xor_sync(0xFFFFFFFFu, m, 2));
        float ssum = 0.f;
        for (int k = k0; k < k1; k++) {
            int idx = k * 64 + ((g ^ (k & 15)) << 2) + qr;
            float p = __expf(sS[idx] - m);
            ssum += p;
            sS[idx] = p;
        }
        ssum += __shfl_xor_sync(0xFFFFFFFFu, ssum, 1);
        ssum += __shfl_xor_sync(0xFFFFFFFFu, ssum, 2);
        if (sub == 0) sIv[q] = 1.f / ssum;
    }
    __syncthreads();

    float* sX0  = sQT;
    float* sX1  = sKV;
    float* sWo  = sS;
    float* sW1h = sS + 4096;
    float* sW2h = sKV + 4096;
    u64t acc2[4][4];
#define ZACC2 \
    _Pragma("unroll") for (int i = 0; i < 4; i++) \
    _Pragma("unroll") for (int j = 0; j < 4; j++) acc2[i][j] = 0ULL;

    {
        const int qt = tid & 15, dt = (tid >> 4) & 7, half = (tid >> 7) & 1;
        ZACC2
        if (tid < 256) {
            gemm2_swz(sS, sKV, qt, dt, half * 96, half ? 5 : 6, acc2);
            if (half) store48(sX0, qt, dt, acc2);
        }
        __syncthreads();
        if (tid < 128) fin_pv48(sX0, sIv, qt, dt, acc2);
    }
    for (int i = tid; i < 1024; i += 384) {
        ((float4*)sWo)[i]  = ((const float4*)wo)[i];
        ((float4*)sW1h)[i] = ((const float4*)n_w1)[i];
        ((float4*)sW2h)[i] = ((const float4*)n_w2)[i];
    }
    __syncthreads();

    const int t128 = tid & 127;
    const int hq = t128 & 15, hd = (t128 >> 4) & 7;
    const int chunk = tid >> 7;
    const int hk0 = (chunk == 0) ? 0 : (chunk == 1 ? 22 : 43);
    const int hkl = (chunk == 0) ? 22 : 21;

    ZACC2
    gemm48_plain(sX0, sWo, hq, hd, hk0, hkl, acc2);
    if (chunk == 1) store48(sX1, hq, hd, acc2);
    else if (chunk == 2) store48_scr(sS, sKV, hq, hd, acc2);
    __syncthreads();
    if (chunk == 0) fin_head3(sX1, sS, sKV, sBo, hq, hd, acc2, false);
    __syncthreads();

    ZACC2
    gemm48_plain(sX1, sW1h, hq, hd, hk0, hkl, acc2);
    if (chunk == 1) store48(sX0, hq, hd, acc2);
    else if (chunk == 2) store48_scr(sS, sKV, hq, hd, acc2);
    __syncthreads();
    if (chunk == 0) fin_head3(sX0, sS, sKV, sB1h, hq, hd, acc2, true);
    __syncthreads();

    ZACC2
    gemm48_plain(sX0, sW2h, hq, hd, hk0, hkl, acc2);
    if (chunk == 1) store48(sX1, hq, hd, acc2);
    else if (chunk == 2) store48_scr(sS, sKV, hq, hd, acc2);
    __syncthreads();
    if (chunk == 0) fin_head3(sX1, sS, sKV, sB2h, hq, hd, acc2, true);
    __syncthreads();

    if (tid < 256) {
        int q = tid >> 2, sub = tid & 3;
        float a = 0.f;
#pragma unroll 4
        for (int dd = 0; dd < 16; dd++) {
            int d = sub * 16 + dd;
            a += sX1[d * 64 + q] * sW3h[d];
        }
        a += __shfl_xor_sync(0xFFFFFFFFu, a, 1);
        a += __shfl_xor_sync(0xFFFFFFFFu, a, 2);
        if (sub == 0) out[b * 128 + qh + q] = tanhf(a + sB3[0]);
    }
}

// ---------------------------------------------------------------------------
extern "C" void kernel_launch(void* const* d_in, const int* in_sizes, int n_in,
                              void* d_out, int out_size)
{
    const float* pred  = (const float*)d_in[0];
    const float* prey  = (const float*)d_in[1];
    const float* obst  = (const float*)d_in[2];
    const void*  alive = d_in[3];
    const float* emb   = (const float*)d_in[4];
    const float* p_w1 = (const float*)d_in[5],  *p_b1 = (const float*)d_in[6];
    const float* p_w2 = (const float*)d_in[7],  *p_b2 = (const float*)d_in[8];
    const float* y_w1 = (const float*)d_in[9],  *y_b1 = (const float*)d_in[10];
    const float* y_w2 = (const float*)d_in[11], *y_b2 = (const float*)d_in[12];
    const float* o_w1 = (const float*)d_in[13], *o_b1 = (const float*)d_in[14];
    const float* o_w2 = (const float*)d_in[15], *o_b2 = (const float*)d_in[16];
    const float* wq = (const float*)d_in[17], *bq = (const float*)d_in[18];
    const float* wk = (const float*)d_in[19], *bk = (const float*)d_in[20];
    const float* wv = (const float*)d_in[21], *bv = (const float*)d_in[22];
    const float* wo = (const float*)d_in[23], *bo = (const float*)d_in[24];
    const float* w_pos = (const float*)d_in[25];
    const float* n_w1 = (const float*)d_in[26], *n_b1 = (const float*)d_in[27];
    const float* n_w2 = (const float*)d_in[28], *n_b2 = (const float*)d_in[29];
    const float* n_w3 = (const float*)d_in[30], *n_b3 = (const float*)d_in[31];
    float* out = (float*)d_out;

    cudaFuncSetAttribute(encode_kernel, cudaFuncAttributeMaxDynamicSharedMemorySize, 13248 * 4);
    cudaFuncSetAttribute(attn_kernel,   cudaFuncAttributeMaxDynamicSharedMemorySize, 28416 * 4);

    encode_kernel<<<2816, 256, 13248 * 4>>>(pred, prey, obst, emb,
        p_w1, p_b1, p_w2, p_b2, y_w1, y_b1, y_w2, y_b2, o_w1, o_b1, o_w2, o_b2,
        wq, bq, wk, bk, wv, bv);
    attn_kernel<<<4096, 384, 28416 * 4>>>(pred, prey, obst, alive, w_pos,
        wo, bo, n_w1, n_b1, n_w2, n_b2, n_w3, n_b3, out);
}

// round 17
// speedup vs baseline: 1.1482x; 1.0044x over previous
#include <cuda_runtime.h>
#include <math.h>

#define NTOK 176

__device__ float g_KT[2048 * 64 * 176];
__device__ float g_V [2048 * 176 * 64];
__device__ float g_QT[2048 * 64 * 128];

#define SWZ(g, r) ((((g) ^ (r) ^ ((r) >> 3))) & 31)

typedef unsigned long long u64t;
__device__ __forceinline__ void fma2(u64t& acc, u64t a, u64t b) {
    asm("fma.rn.f32x2 %0, %1, %2, %0;" : "+l"(acc) : "l"(a), "l"(b));
}
__device__ __forceinline__ u64t bc2(float x) {
    u64t r; unsigned int xi = __float_as_uint(x);
    asm("mov.b64 %0, {%1, %1};" : "=l"(r) : "r"(xi));
    return r;
}
__device__ __forceinline__ float2 up2(u64t v) {
    float2 r; asm("mov.b64 {%0, %1}, %2;" : "=f"(r.x), "=f"(r.y) : "l"(v));
    return r;
}

// ---------------------------------------------------------------------------
// Kernel 1 body, fully specialized per entity type (compile-time IN_DIM etc.)
// ---------------------------------------------------------------------------
template<int TYPE, int IN_DIM, int PER_SHIFT, int SLOT_BASE>
__device__ __forceinline__ void encode_body(
    int tok0, const float* __restrict__ state,
    const float* __restrict__ w1, const float* __restrict__ b1,
    const float* __restrict__ w2, const float* __restrict__ b2,
    const float* __restrict__ emb,
    const float* __restrict__ wq, const float* __restrict__ bq,
    const float* __restrict__ wk, const float* __restrict__ bk,
    const float* __restrict__ wv, const float* __restrict__ bv,
    float* __restrict__ sm)
{
    float* sW  = sm;
    float* sX  = sm + 4096;
    float* sC  = sm + 12288;
    float* sBK = sm + 12352;
    float* sBV = sm + 12416;
    float* sBQ = sm + 12480;
    float* sB1 = sm + 12544;
    float* sW1 = sm + 12608;
    float* sSt = sm + 12800;

    const int tid = threadIdx.x;

    for (int i = tid; i < 1024; i += 256)
        ((float4*)sW)[i] = ((const float4*)w2)[i];
    if (tid < 64) {
        sC[tid]  = b2[tid] + emb[TYPE * 64 + tid];
        sBK[tid] = bk[tid]; sBV[tid] = bv[tid]; sBQ[tid] = bq[tid]; sB1[tid] = b1[tid];
    }
    if (tid < IN_DIM * 64) sW1[tid] = w1[tid];
#pragma unroll
    for (int r = 0; r < (128 * IN_DIM + 255) / 256; r++) {
        int i = r * 256 + tid;
        if (i < 128 * IN_DIM) {
            int t = i / IN_DIM, j = i - t * IN_DIM;
            sSt[t * 3 + j] = state[(tok0 + t) * IN_DIM + j];
        }
    }
    __syncthreads();

    const int dg = tid & 7, tg = tid >> 3, ds = dg * 8;

    u64t accX[4][4];
#pragma unroll
    for (int i = 0; i < 4; i++)
#pragma unroll
        for (int j = 0; j < 4; j++) accX[i][j] = 0ULL;

#pragma unroll 1
    for (int h = 0; h < 2; h++) {
        for (int e = tid; e < 4096; e += 256) {
            int k = e >> 7, t = e & 127;
            int gk = h * 32 + k;
            float a = sB1[gk];
#pragma unroll
            for (int j = 0; j < IN_DIM; j++) a += sSt[t * 3 + j] * sW1[j * 64 + gk];
            sX[k * 128 + t] = fmaxf(a, 0.f);
        }
        __syncthreads();
#pragma unroll 4
        for (int kk = 0; kk < 32; kk++) {
            float4 a4 = *(const float4*)(sX + kk * 128 + tg * 4);
            const float* wr = sW + (h * 32 + kk) * 64 + ds;
            ulonglong2 w01 = *(const ulonglong2*)(wr);
            ulonglong2 w23 = *(const ulonglong2*)(wr + 4);
            u64t bw[4] = {w01.x, w01.y, w23.x, w23.y};
            u64t av[4] = {bc2(a4.x), bc2(a4.y), bc2(a4.z), bc2(a4.w)};
#pragma unroll
            for (int i = 0; i < 4; i++)
#pragma unroll
                for (int j = 0; j < 4; j++) fma2(accX[i][j], av[i], bw[j]);
        }
        __syncthreads();
    }

#pragma unroll
    for (int j2 = 0; j2 < 4; j2++) {
        int d0 = ds + 2 * j2, d1 = d0 + 1;
        float c0 = sC[d0], c1 = sC[d1];
        float2 u0 = up2(accX[0][j2]), u1 = up2(accX[1][j2]);
        float2 u2 = up2(accX[2][j2]), u3 = up2(accX[3][j2]);
        *(float4*)(sX + d0 * 128 + SWZ(tg, d0) * 4) =
            make_float4(u0.x + c0, u1.x + c0, u2.x + c0, u3.x + c0);
        *(float4*)(sX + d1 * 128 + SWZ(tg, d1) * 4) =
            make_float4(u0.y + c1, u1.y + c1, u2.y + c1, u3.y + c1);
    }
    for (int i = tid; i < 1024; i += 256)
        ((float4*)sW)[i] = ((const float4*)wk)[i];
    __syncthreads();

    const int gT   = tok0 + tg * 4;
    const int b    = gT >> PER_SHIFT;
    const int lp   = gT & ((1 << PER_SHIFT) - 1);
    const int slot = SLOT_BASE + lp;

    {
        u64t aK[4][4];
#pragma unroll
        for (int i = 0; i < 4; i++)
#pragma unroll
            for (int j = 0; j < 4; j++) aK[i][j] = 0ULL;
#pragma unroll 4
        for (int k = 0; k < 64; k++) {
            float4 a4 = *(const float4*)(sX + k * 128 + SWZ(tg, k) * 4);
            const float* kr = sW + k * 64 + ds;
            ulonglong2 k01 = *(const ulonglong2*)(kr);
            ulonglong2 k23 = *(const ulonglong2*)(kr + 4);
            u64t kw[4] = {k01.x, k01.y, k23.x, k23.y};
            u64t av[4] = {bc2(a4.x), bc2(a4.y), bc2(a4.z), bc2(a4.w)};
#pragma unroll
            for (int i = 0; i < 4; i++)
#pragma unroll
                for (int j = 0; j < 4; j++) fma2(aK[i][j], av[i], kw[j]);
        }
#pragma unroll
        for (int j2 = 0; j2 < 4; j2++) {
            int d0 = ds + 2 * j2, d1 = d0 + 1;
            float b0 = sBK[d0], b1v = sBK[d1];
            float2 u0 = up2(aK[0][j2]), u1 = up2(aK[1][j2]);
            float2 u2 = up2(aK[2][j2]), u3 = up2(aK[3][j2]);
            *(float4*)(g_KT + (b * 64 + d0) * 176 + slot) =
                make_float4(u0.x + b0, u1.x + b0, u2.x + b0, u3.x + b0);
            *(float4*)(g_KT + (b * 64 + d1) * 176 + slot) =
                make_float4(u0.y + b1v, u1.y + b1v, u2.y + b1v, u3.y + b1v);
        }
    }
    __syncthreads();
    for (int i = tid; i < 1024; i += 256)
        ((float4*)sW)[i] = ((const float4*)wv)[i];
    __syncthreads();

    {
        u64t aV[4][4];
#pragma unroll
        for (int i = 0; i < 4; i++)
#pragma unroll
            for (int j = 0; j < 4; j++) aV[i][j] = 0ULL;
#pragma unroll 4
        for (int k = 0; k < 64; k++) {
            float4 a4 = *(const float4*)(sX + k * 128 + SWZ(tg, k) * 4);
            const float* vr = sW + k * 64 + ds;
            ulonglong2 v01 = *(const ulonglong2*)(vr);
            ulonglong2 v23 = *(const ulonglong2*)(vr + 4);
            u64t vw[4] = {v01.x, v01.y, v23.x, v23.y};
            u64t av[4] = {bc2(a4.x), bc2(a4.y), bc2(a4.z), bc2(a4.w)};
#pragma unroll
            for (int i = 0; i < 4; i++)
#pragma unroll
                for (int j = 0; j < 4; j++) fma2(aV[i][j], av[i], vw[j]);
        }
#pragma unroll
        for (int i = 0; i < 4; i++) {
            int row = (b * 176 + slot + i) * 64;
            float2 v0 = up2(aV[i][0]), v1 = up2(aV[i][1]);
            float2 v2 = up2(aV[i][2]), v3 = up2(aV[i][3]);
            *(float4*)(g_V + row + ds) =
                make_float4(v0.x + sBV[ds], v0.y + sBV[ds + 1], v1.x + sBV[ds + 2], v1.y + sBV[ds + 3]);
            *(float4*)(g_V + row + ds + 4) =
                make_float4(v2.x + sBV[ds + 4], v2.y + sBV[ds + 5], v3.x + sBV[ds + 6], v3.y + sBV[ds + 7]);
        }
    }

    if (TYPE == 1) {
        __syncthreads();
        for (int i = tid; i < 1024; i += 256)
            ((float4*)sW)[i] = ((const float4*)wq)[i];
        __syncthreads();
        u64t aQ[4][4];
#pragma unroll
        for (int i = 0; i < 4; i++)
#pragma unroll
            for (int j = 0; j < 4; j++) aQ[i][j] = 0ULL;
#pragma unroll 4
        for (int k = 0; k < 64; k++) {
            float4 a4 = *(const float4*)(sX + k * 128 + SWZ(tg, k) * 4);
            const float* qr = sW + k * 64 + ds;
            ulonglong2 q01 = *(const ulonglong2*)(qr);
            ulonglong2 q23 = *(const ulonglong2*)(qr + 4);
            u64t qw[4] = {q01.x, q01.y, q23.x, q23.y};
            u64t av[4] = {bc2(a4.x), bc2(a4.y), bc2(a4.z), bc2(a4.w)};
#pragma unroll
            for (int i = 0; i < 4; i++)
#pragma unroll
                for (int j = 0; j < 4; j++) fma2(aQ[i][j], av[i], qw[j]);
        }
#pragma unroll
        for (int j2 = 0; j2 < 4; j2++) {
            int d0 = ds + 2 * j2, d1 = d0 + 1;
            float b0 = sBQ[d0], b1v = sBQ[d1];
            float2 u0 = up2(aQ[0][j2]), u1 = up2(aQ[1][j2]);
            float2 u2 = up2(aQ[2][j2]), u3 = up2(aQ[3][j2]);
            *(float4*)(g_QT + (b * 64 + d0) * 128 + lp) =
                make_float4(u0.x + b0, u1.x + b0, u2.x + b0, u3.x + b0);
            *(float4*)(g_QT + (b * 64 + d1) * 128 + lp) =
                make_float4(u0.y + b1v, u1.y + b1v, u2.y + b1v, u3.y + b1v);
        }
    }
}

__global__ void __launch_bounds__(256, 4) encode_kernel(
    const float* __restrict__ pred_state, const float* __restrict__ prey_state,
    const float* __restrict__ obst_state, const float* __restrict__ emb,
    const float* __restrict__ p_w1, const float* __restrict__ p_b1,
    const float* __restrict__ p_w2, const float* __restrict__ p_b2,
    const float* __restrict__ y_w1, const float* __restrict__ y_b1,
    const float* __restrict__ y_w2, const float* __restrict__ y_b2,
    const float* __restrict__ o_w1, const float* __restrict__ o_b1,
    const float* __restrict__ o_w2, const float* __restrict__ o_b2,
    const float* __restrict__ wq, const float* __restrict__ bq,
    const float* __restrict__ wk, const float* __restrict__ bk,
    const float* __restrict__ wv, const float* __restrict__ bv)
{
    extern __shared__ float sm[];
    const int blk = blockIdx.x;
    if (blk < 256)
        encode_body<0, 2, 4, 0>(blk * 128, pred_state, p_w1, p_b1, p_w2, p_b2,
                                emb, wq, bq, wk, bk, wv, bv, sm);
    else if (blk < 2304)
        encode_body<1, 2, 7, 16>((blk - 256) * 128, prey_state, y_w1, y_b1, y_w2, y_b2,
                                 emb, wq, bq, wk, bk, wv, bv, sm);
    else
        encode_body<2, 3, 5, 144>((blk - 2304) * 128, obst_state, o_w1, o_b1, o_w2, o_b2,
                                  emb, wq, bq, wk, bk, wv, bv, sm);
}

// ---------------------------------------------------------------------------
// post-softmax helpers (unchanged 919us version). X buffers plain.
// ---------------------------------------------------------------------------
__device__ __forceinline__ void gemm48_plain(
    const float* __restrict__ A, const float* __restrict__ W,
    int qt, int dt, int k0, int klen, u64t acc[4][4])
{
#pragma unroll 4
    for (int kk = 0; kk < klen; kk++) {
        int k = k0 + kk;
        float4 a4 = *(const float4*)(A + k * 64 + (qt << 2));
        ulonglong2 w01 = *(const ulonglong2*)(W + k * 64 + dt * 8);
        ulonglong2 w23 = *(const ulonglong2*)(W + k * 64 + dt * 8 + 4);
        u64t wv4[4] = {w01.x, w01.y, w23.x, w23.y};
        u64t av[4] = {bc2(a4.x), bc2(a4.y), bc2(a4.z), bc2(a4.w)};
#pragma unroll
        for (int i = 0; i < 4; i++)
#pragma unroll
            for (int j = 0; j < 4; j++) fma2(acc[i][j], av[i], wv4[j]);
    }
}

__device__ __forceinline__ void gemm2_swz(
    const float* __restrict__ A, const float* __restrict__ W,
    int qt, int dt, int k0, int nblk, u64t acc[4][4])
{
#pragma unroll 1
    for (int blk = 0; blk < nblk; blk++) {
        const float* Ab = A + (k0 + blk * 16) * 64;
        const float* Wb = W + (k0 + blk * 16) * 64 + dt * 8;
#pragma unroll
        for (int kk = 0; kk < 16; kk++) {
            float4 a4 = *(const float4*)(Ab + kk * 64 + ((qt ^ kk) << 2));
            ulonglong2 w01 = *(const ulonglong2*)(Wb + kk * 64);
            ulonglong2 w23 = *(const ulonglong2*)(Wb + kk * 64 + 4);
            u64t wv4[4] = {w01.x, w01.y, w23.x, w23.y};
            u64t av[4] = {bc2(a4.x), bc2(a4.y), bc2(a4.z), bc2(a4.w)};
#pragma unroll
            for (int i = 0; i < 4; i++)
#pragma unroll
                for (int j = 0; j < 4; j++) fma2(acc[i][j], av[i], wv4[j]);
        }
    }
}

__device__ __forceinline__ float* scr_ptr(float* sS, float* sKV, int d, int off) {
    return (d < 48) ? (sS + 8192 + d * 64 + off) : (sKV + 8192 + (d - 48) * 64 + off);
}

__device__ __forceinline__ void store48(
    float* __restrict__ Out, int qt, int dt, u64t acc[4][4])
{
#pragma unroll
    for (int j = 0; j < 4; j++) {
        int d0 = dt * 8 + 2 * j, d1 = d0 + 1;
        float2 p0 = up2(acc[0][j]), p1 = up2(acc[1][j]);
        float2 p2 = up2(acc[2][j]), p3 = up2(acc[3][j]);
        *(float4*)(Out + d0 * 64 + (qt << 2)) = make_float4(p0.x, p1.x, p2.x, p3.x);
        *(float4*)(Out + d1 * 64 + (qt << 2)) = make_float4(p0.y, p1.y, p2.y, p3.y);
    }
}

__device__ __forceinline__ void store48_scr(
    float* sS, float* sKV, int qt, int dt, u64t acc[4][4])
{
#pragma unroll
    for (int j = 0; j < 4; j++) {
        int d0 = dt * 8 + 2 * j, d1 = d0 + 1;
        float2 p0 = up2(acc[0][j]), p1 = up2(acc[1][j]);
        float2 p2 = up2(acc[2][j]), p3 = up2(acc[3][j]);
        *(float4*)scr_ptr(sS, sKV, d0, qt << 2) = make_float4(p0.x, p1.x, p2.x, p3.x);
        *(float4*)scr_ptr(sS, sKV, d1, qt << 2) = make_float4(p0.y, p1.y, p2.y, p3.y);
    }
}

__device__ __forceinline__ void fin_head3(
    float* __restrict__ Out, float* sS, float* sKV,
    const float* __restrict__ bias,
    int qt, int dt, u64t acc[4][4], bool relu)
{
#pragma unroll
    for (int j = 0; j < 4; j++) {
        int d0 = dt * 8 + 2 * j, d1 = d0 + 1;
        float b0 = bias[d0], b1 = bias[d1];
        float* a0 = Out + d0 * 64 + (qt << 2);
        float* a1 = Out + d1 * 64 + (qt << 2);
        float4 o0 = *(float4*)a0, o1 = *(float4*)a1;
        float4 s0 = *(float4*)scr_ptr(sS, sKV, d0, qt << 2);
        float4 s1 = *(float4*)scr_ptr(sS, sKV, d1, qt << 2);
        float2 p0 = up2(acc[0][j]), p1 = up2(acc[1][j]);
        float2 p2 = up2(acc[2][j]), p3 = up2(acc[3][j]);
        o0.x += s0.x + p0.x + b0; o0.y += s0.y + p1.x + b0;
        o0.z += s0.z + p2.x + b0; o0.w += s0.w + p3.x + b0;
        o1.x += s1.x + p0.y + b1; o1.y += s1.y + p1.y + b1;
        o1.z += s1.z + p2.y + b1; o1.w += s1.w + p3.y + b1;
        if (relu) {
            o0.x = fmaxf(o0.x, 0.f); o0.y = fmaxf(o0.y, 0.f);
            o0.z = fmaxf(o0.z, 0.f); o0.w = fmaxf(o0.w, 0.f);
            o1.x = fmaxf(o1.x, 0.f); o1.y = fmaxf(o1.y, 0.f);
            o1.z = fmaxf(o1.z, 0.f); o1.w = fmaxf(o1.w, 0.f);
        }
        *(float4*)a0 = o0; *(float4*)a1 = o1;
    }
}

__device__ __forceinline__ void fin_pv48(
    float* __restrict__ Out, const float* __restrict__ sIv,
    int qt, int dt, u64t acc[4][4])
{
    float iv[4] = {sIv[qt * 4], sIv[qt * 4 + 1], sIv[qt * 4 + 2], sIv[qt * 4 + 3]};
#pragma unroll
    for (int j = 0; j < 4; j++) {
        int d0 = dt * 8 + 2 * j, d1 = d0 + 1;
        float* a0 = Out + d0 * 64 + (qt << 2);
        float* a1 = Out + d1 * 64 + (qt << 2);
        float4 o0 = *(float4*)a0, o1 = *(float4*)a1;
        float2 p0 = up2(acc[0][j]), p1 = up2(acc[1][j]);
        float2 p2 = up2(acc[2][j]), p3 = up2(acc[3][j]);
        o0.x = (o0.x + p0.x) * iv[0]; o0.y = (o0.y + p1.x) * iv[1];
        o0.z = (o0.z + p2.x) * iv[2]; o0.w = (o0.w + p3.x) * iv[3];
        o1.x = (o1.x + p0.y) * iv[0]; o1.y = (o1.y + p1.y) * iv[1];
        o1.z = (o1.z + p2.y) * iv[2]; o1.w = (o1.w + p3.y) * iv[3];
        *(float4*)a0 = o0; *(float4*)a1 = o1;
    }
}

// ---------------------------------------------------------------------------
// Kernel 2: attention + head (unchanged 919us version).
// ---------------------------------------------------------------------------
__global__ void __launch_bounds__(384, 2) attn_kernel(
    const float* __restrict__ pred_state, const float* __restrict__ prey_state,
    const float* __restrict__ obst_state, const void* __restrict__ alive,
    const float* __restrict__ w_pos,
    const float* __restrict__ wo,   const float* __restrict__ bo,
    const float* __restrict__ n_w1, const float* __restrict__ n_b1,
    const float* __restrict__ n_w2, const float* __restrict__ n_b2,
    const float* __restrict__ n_w3, const float* __restrict__ n_b3,
    float* __restrict__ out)
{
    extern __shared__ float sm[];
    float* sKV = sm;
    float* sQT = sm + 12288;
    float* sS  = sm + 16384;
    float* sBK = sm + 27648;
    float* sMK = sm + 27824;
    float* sDQ = sm + 28000;
    float* sIv = sm + 28064;
    float* sBo = sm + 28128;
    float* sB1h= sm + 28192;
    float* sB2h= sm + 28256;
    float* sW3h= sm + 28320;
    float* sB3 = sm + 28384;
    __shared__ int sFl[2];

    const int tid = threadIdx.x;
    const int b   = blockIdx.x >> 1;
    const int qh  = (blockIdx.x & 1) << 6;

    if (tid == 0) { sFl[0] = 0; sFl[1] = 0; }
    __syncthreads();

    {
        const float4* gk = (const float4*)(g_KT + b * 11264);
        for (int i = tid; i < 2816; i += 384) {
            int d = i / 44, c = i - d * 44;
            *(float4*)(sKV + d * 192 + c * 4) = gk[i];
        }
        for (int i = tid; i < 1024; i += 384) {
            int d = i >> 4, c = i & 15;
            *(float4*)(sQT + d * 64 + c * 4) =
                *(const float4*)(g_QT + b * 8192 + d * 128 + qh + c * 4);
        }
        if (tid < 64) {
            sBo[tid] = bo[tid]; sB1h[tid] = n_b1[tid];
            sB2h[tid] = n_b2[tid]; sW3h[tid] = n_w3[tid];
        }
        if (tid == 0) sB3[0] = n_b3[0];
        if (tid < 128) {
            unsigned int v = ((const unsigned int*)alive)[tid];
            if (v == 0x3F800000u) atomicOr(&sFl[0], 1);
            else if (v > 1u)      atomicOr(&sFl[1], 1);
        }
    }
    __syncthreads();
    const int fmt = sFl[0] ? 2 : (sFl[1] ? 0 : 1);

    if (tid < NTOK) {
        int k = tid;
        float p0, p1, mk = 0.f;
        if (k < 16) {
            p0 = pred_state[(b * 16 + k) * 2];
            p1 = pred_state[(b * 16 + k) * 2 + 1];
        } else if (k < 144) {
            int j = k - 16;
            p0 = prey_state[(b * 128 + j) * 2];
            p1 = prey_state[(b * 128 + j) * 2 + 1];
            bool al;
            if (fmt == 0)      al = ((const unsigned char*)alive)[b * 128 + j] != 0;
            else if (fmt == 1) al = ((const int*)alive)[b * 128 + j] != 0;
            else               al = ((const float*)alive)[b * 128 + j] != 0.f;
            if (!al) mk = -1e9f;
        } else {
            int j = k - 144;
            p0 = obst_state[(b * 32 + j) * 3];
            p1 = obst_state[(b * 32 + j) * 3 + 1];
        }
        sBK[k] = p0 * w_pos[0] + p1 * w_pos[1];
        sMK[k] = mk;
    }
    if (tid >= 192 && tid < 256) {
        int q = qh + tid - 192;
        bool al;
        if (fmt == 0)      al = ((const unsigned char*)alive)[b * 128 + q] != 0;
        else if (fmt == 1) al = ((const int*)alive)[b * 128 + q] != 0;
        else               al = ((const float*)alive)[b * 128 + q] != 0.f;
        sDQ[tid - 192] = al ? 0.f : 1.f;
    }
    __syncthreads();

    if (tid < 352) {
        const int kg = tid >> 4, qg = tid & 15;
        u64t acc[4][4];
#pragma unroll
        for (int p = 0; p < 4; p++)
#pragma unroll
            for (int j = 0; j < 4; j++) acc[p][j] = 0ULL;
#pragma unroll 4
        for (int d = 0; d < 64; d++) {
            const float* kr = sKV + d * 192 + kg * 8;
            ulonglong2 kA = *(const ulonglong2*)(kr);
            ulonglong2 kB = *(const ulonglong2*)(kr + 4);
            float4 q4 = *(const float4*)(sQT + d * 64 + qg * 4);
            u64t kp[4] = {kA.x, kA.y, kB.x, kB.y};
            u64t qb[4] = {bc2(q4.x), bc2(q4.y), bc2(q4.z), bc2(q4.w)};
#pragma unroll
            for (int p = 0; p < 4; p++)
#pragma unroll
                for (int j = 0; j < 4; j++) fma2(acc[p][j], kp[p], qb[j]);
        }
        float dq[4] = {sDQ[qg * 4], sDQ[qg * 4 + 1], sDQ[qg * 4 + 2], sDQ[qg * 4 + 3]};
#pragma unroll
        for (int p = 0; p < 4; p++) {
            int r0 = kg * 8 + 2 * p, r1 = r0 + 1;
            float2 u0 = up2(acc[p][0]), u1 = up2(acc[p][1]);
            float2 u2 = up2(acc[p][2]), u3 = up2(acc[p][3]);
            float bk0 = sBK[r0], mk0 = sMK[r0];
            float bk1 = sBK[r1], mk1 = sMK[r1];
            *(float4*)(sS + r0 * 64 + ((qg ^ (r0 & 15)) << 2)) =
                make_float4((u0.x - bk0) * 0.125f + dq[0] * mk0,
                            (u1.x - bk0) * 0.125f + dq[1] * mk0,
                            (u2.x - bk0) * 0.125f + dq[2] * mk0,
                            (u3.x - bk0) * 0.125f + dq[3] * mk0);
            *(float4*)(sS + r1 * 64 + ((qg ^ (r1 & 15)) << 2)) =
                make_float4((u0.y - bk1) * 0.125f + dq[0] * mk1,
                            (u1.y - bk1) * 0.125f + dq[1] * mk1,
                            (u2.y - bk1) * 0.125f + dq[2] * mk1,
                            (u3.y - bk1) * 0.125f + dq[3] * mk1);
        }
    }
    __syncthreads();

    {
        const float4* gv = (const float4*)(g_V + b * 11264);
        float4* dv = (float4*)sKV;
        for (int i = tid; i < 2816; i += 384) dv[i] = gv[i];
    }
    if (tid < 256) {
        int q = tid >> 2, sub = tid & 3;
        int g = q >> 2, qr = q & 3;
        int k0 = sub * 44, k1 = k0 + 44;
        float m = -3.4e38f;
        for (int k = k0; k < k1; k++)
            m = fmaxf(m, sS[k * 64 + ((g ^ (k & 15)) << 2) + qr]);
        m = fmaxf(m, __shfl_xor_sync(0xFFFFFFFFu, m, 1));
        m = fmaxf(m, __shfl_xor_sync(0xFFFFFFFFu, m, 2));
        float ssum = 0.f;
        for (int k = k0; k < k1; k++) {
            int idx = k * 64 + ((g ^ (k & 15)) << 2) + qr;
            float p = __expf(sS[idx] - m);
            ssum += p;
            sS[idx] = p;
        }
        ssum += __shfl_xor_sync(0xFFFFFFFFu, ssum, 1);
        ssum += __shfl_xor_sync(0xFFFFFFFFu, ssum, 2);
        if (sub == 0) sIv[q] = 1.f / ssum;
    }
    __syncthreads();

    float* sX0  = sQT;
    float* sX1  = sKV;
    float* sWo  = sS;
    float* sW1h = sS + 4096;
    float* sW2h = sKV + 4096;
    u64t acc2[4][4];
#define ZACC2 \
    _Pragma("unroll") for (int i = 0; i < 4; i++) \
    _Pragma("unroll") for (int j = 0; j < 4; j++) acc2[i][j] = 0ULL;

    {
        const int qt = tid & 15, dt = (tid >> 4) & 7, half = (tid >> 7) & 1;
        ZACC2
        if (tid < 256) {
            gemm2_swz(sS, sKV, qt, dt, half * 96, half ? 5 : 6, acc2);
            if (half) store48(sX0, qt, dt, acc2);
        }
        __syncthreads();
        if (tid < 128) fin_pv48(sX0, sIv, qt, dt, acc2);
    }
    for (int i = tid; i < 1024; i += 384) {
        ((float4*)sWo)[i]  = ((const float4*)wo)[i];
        ((float4*)sW1h)[i] = ((const float4*)n_w1)[i];
        ((float4*)sW2h)[i] = ((const float4*)n_w2)[i];
    }
    __syncthreads();

    const int t128 = tid & 127;
    const int hq = t128 & 15, hd = (t128 >> 4) & 7;
    const int chunk = tid >> 7;
    const int hk0 = (chunk == 0) ? 0 : (chunk == 1 ? 22 : 43);
    const int hkl = (chunk == 0) ? 22 : 21;

    ZACC2
    gemm48_plain(sX0, sWo, hq, hd, hk0, hkl, acc2);
    if (chunk == 1) store48(sX1, hq, hd, acc2);
    else if (chunk == 2) store48_scr(sS, sKV, hq, hd, acc2);
    __syncthreads();
    if (chunk == 0) fin_head3(sX1, sS, sKV, sBo, hq, hd, acc2, false);
    __syncthreads();

    ZACC2
    gemm48_plain(sX1, sW1h, hq, hd, hk0, hkl, acc2);
    if (chunk == 1) store48(sX0, hq, hd, acc2);
    else if (chunk == 2) store48_scr(sS, sKV, hq, hd, acc2);
    __syncthreads();
    if (chunk == 0) fin_head3(sX0, sS, sKV, sB1h, hq, hd, acc2, true);
    __syncthreads();

    ZACC2
    gemm48_plain(sX0, sW2h, hq, hd, hk0, hkl, acc2);
    if (chunk == 1) store48(sX1, hq, hd, acc2);
    else if (chunk == 2) store48_scr(sS, sKV, hq, hd, acc2);
    __syncthreads();
    if (chunk == 0) fin_head3(sX1, sS, sKV, sB2h, hq, hd, acc2, true);
    __syncthreads();

    if (tid < 256) {
        int q = tid >> 2, sub = tid & 3;
        float a = 0.f;
#pragma unroll 4
        for (int dd = 0; dd < 16; dd++) {
            int d = sub * 16 + dd;
            a += sX1[d * 64 + q] * sW3h[d];
        }
        a += __shfl_xor_sync(0xFFFFFFFFu, a, 1);
        a += __shfl_xor_sync(0xFFFFFFFFu, a, 2);
        if (sub == 0) out[b * 128 + qh + q] = tanhf(a + sB3[0]);
    }
}

// ---------------------------------------------------------------------------
extern "C" void kernel_launch(void* const* d_in, const int* in_sizes, int n_in,
                              void* d_out, int out_size)
{
    const float* pred  = (const float*)d_in[0];
    const float* prey  = (const float*)d_in[1];
    const float* obst  = (const float*)d_in[2];
    const void*  alive = d_in[3];
    const float* emb   = (const float*)d_in[4];
    const float* p_w1 = (const float*)d_in[5],  *p_b1 = (const float*)d_in[6];
    const float* p_w2 = (const float*)d_in[7],  *p_b2 = (const float*)d_in[8];
    const float* y_w1 = (const float*)d_in[9],  *y_b1 = (const float*)d_in[10];
    const float* y_w2 = (const float*)d_in[11], *y_b2 = (const float*)d_in[12];
    const float* o_w1 = (const float*)d_in[13], *o_b1 = (const float*)d_in[14];
    const float* o_w2 = (const float*)d_in[15], *o_b2 = (const float*)d_in[16];
    const float* wq = (const float*)d_in[17], *bq = (const float*)d_in[18];
    const float* wk = (const float*)d_in[19], *bk = (const float*)d_in[20];
    const float* wv = (const float*)d_in[21], *bv = (const float*)d_in[22];
    const float* wo = (const float*)d_in[23], *bo = (const float*)d_in[24];
    const float* w_pos = (const float*)d_in[25];
    const float* n_w1 = (const float*)d_in[26], *n_b1 = (const float*)d_in[27];
    const float* n_w2 = (const float*)d_in[28], *n_b2 = (const float*)d_in[29];
    const float* n_w3 = (const float*)d_in[30], *n_b3 = (const float*)d_in[31];
    float* out = (float*)d_out;

    cudaFuncSetAttribute(encode_kernel, cudaFuncAttributeMaxDynamicSharedMemorySize, 13248 * 4);
    cudaFuncSetAttribute(attn_kernel,   cudaFuncAttributeMaxDynamicSharedMemorySize, 28416 * 4);

    encode_kernel<<<2816, 256, 13248 * 4>>>(pred, prey, obst, emb,
        p_w1, p_b1, p_w2, p_b2, y_w1, y_b1, y_w2, y_b2, o_w1, o_b1, o_w2, o_b2,
        wq, bq, wk, bk, wv, bv);
    attn_kernel<<<4096, 384, 28416 * 4>>>(pred, prey, obst, alive, w_pos,
        wo, bo, n_w1, n_b1, n_w2, n_b2, n_w3, n_b3, out);
}